// round 1
// baseline (speedup 1.0000x reference)
#include <cuda_runtime.h>
#include <cuda_bf16.h>
#include <math.h>

// ---------------- problem constants ----------------
#define Bn    32
#define Gn    512
#define Cn    768
#define Hn    12
#define HD    64
#define Tn    513              // G+1
#define MROWS (Bn*Tn)          // 16416
#define BG    16384
#define FFn   3072
#define ADn   16
#define MIDn  12
#define H1n   6
#define N1n   128
#define NB1   (BG/N1n)         // 128
#define NCL   2048
#define D1n   6272
#define NV    6
#define EPSf  1e-5f

// ---------------- scratch (device globals; no allocation) ----------------
__device__ float  g_y   [MROWS*Cn];
__device__ float  g_qkv [MROWS*3*Cn];
__device__ float  g_att [MROWS*Cn];
__device__ float  g_x1  [MROWS*Cn];
__device__ float  g_hfc [MROWS*FFn];
__device__ float  g_xffn[MROWS*Cn];
__device__ float  g_x2  [MROWS*Cn];
__device__ float  g_segmax[D1n*Cn];
__device__ float  g_segsum[D1n*Cn];
__device__ int    g_segcnt[D1n];
__device__ float  g_scomb [D1n*Cn];
__device__ double g_colsum[Cn];
__device__ double g_colsq [Cn];
__device__ float  g_mean[Cn];
__device__ float  g_rstd[Cn];
__device__ float  g_g3   [NCL*Cn];
__device__ float  g_bview[NV*D1n*Cn];
__device__ float  g_z    [BG*Cn];
__device__ float  g_qkv1 [BG*36];
__device__ float  g_o1   [BG*MIDn];
__device__ float  g_flat [BG*Cn];

// ---------------- helpers ----------------
__device__ __forceinline__ void atomicMaxF(float* addr, float val) {
    int* ia = (int*)addr;
    int old = *ia;
    while (__int_as_float(old) < val) {
        int assumed = old;
        old = atomicCAS(ia, assumed, __float_as_int(val));
        if (old == assumed) break;
    }
}

__device__ __forceinline__ float blockReduceSum256(float v, float* red) {
    int tid = threadIdx.x;
    red[tid] = v; __syncthreads();
    #pragma unroll
    for (int o = 128; o > 0; o >>= 1) {
        if (tid < o) red[tid] += red[tid + o];
        __syncthreads();
    }
    float r = red[0];
    __syncthreads();
    return r;
}

__device__ __forceinline__ float quick_gelu(float x) {
    return x / (1.f + expf(-1.702f * x));
}
__device__ __forceinline__ float gelu_exact(float x) {
    return 0.5f * x * (1.f + erff(x * 0.70710678118654752f));
}
__device__ __forceinline__ int featRow(int i) { // i in [0,BG) -> row in (B,513) layout
    return (i >> 9) * Tn + 1 + (i & 511);
}

// ---------------- LayerNorm (two-pass, block per row) ----------------
__global__ void ln_kernel(const float* __restrict__ in, const float* __restrict__ g,
                          const float* __restrict__ b, float* __restrict__ out, int featmode)
{
    int r = blockIdx.x;
    int row = featmode ? featRow(r) : r;
    const float* x = in + (size_t)row * Cn;
    __shared__ float xs[Cn];
    __shared__ float red[256];
    int tid = threadIdx.x;
    float s0 = 0.f;
    for (int c = tid; c < Cn; c += 256) { float v = x[c]; xs[c] = v; s0 += v; }
    float mean = blockReduceSum256(s0, red) * (1.f / Cn);
    float s1 = 0.f;
    for (int c = tid; c < Cn; c += 256) { float d = xs[c] - mean; s1 += d * d; }
    float var = blockReduceSum256(s1, red) * (1.f / Cn);
    float inv = rsqrtf(var + EPSf);
    float* op = out + (size_t)r * Cn;
    for (int c = tid; c < Cn; c += 256)
        op[c] = (xs[c] - mean) * inv * g[c] + b[c];
}

// ---------------- generic NT SGEMM: C[M,N] = A[M,K] @ W[N,K]^T + bias (+epi) ----------------
// EPI: 0 = bias, 1 = bias + quick_gelu, 2 = bias + residual
template <int EPI>
__global__ void gemm_nt(const float* __restrict__ A, const float* __restrict__ W,
                        const float* __restrict__ bias, const float* __restrict__ res,
                        float* __restrict__ C, int M, int N, int K)
{
    __shared__ float As[8][128];
    __shared__ float Bs[8][128];
    int tid = threadIdx.x;
    int tx = tid & 15, ty = tid >> 4;
    int bm = blockIdx.x * 128, bn = blockIdx.y * 128;
    float acc[8][8];
    #pragma unroll
    for (int i = 0; i < 8; i++)
        #pragma unroll
        for (int j = 0; j < 8; j++) acc[i][j] = 0.f;

    int lr = tid >> 1;            // 0..127
    int lk = (tid & 1) * 4;       // 0 or 4

    for (int k0 = 0; k0 < K; k0 += 8) {
        int am = bm + lr;
        const float* ap = A + (size_t)am * K + k0 + lk;
        bool av = (am < M);
        #pragma unroll
        for (int i = 0; i < 4; i++) As[lk + i][lr] = av ? ap[i] : 0.f;
        int wn = bn + lr;
        const float* wp = W + (size_t)wn * K + k0 + lk;
        bool wv = (wn < N);
        #pragma unroll
        for (int i = 0; i < 4; i++) Bs[lk + i][lr] = wv ? wp[i] : 0.f;
        __syncthreads();
        #pragma unroll
        for (int k = 0; k < 8; k++) {
            float a[8], bb[8];
            const float4* a4 = (const float4*)&As[k][ty * 8];
            const float4* b4 = (const float4*)&Bs[k][tx * 8];
            float4 t0 = a4[0], t1 = a4[1];
            a[0]=t0.x; a[1]=t0.y; a[2]=t0.z; a[3]=t0.w;
            a[4]=t1.x; a[5]=t1.y; a[6]=t1.z; a[7]=t1.w;
            float4 u0 = b4[0], u1 = b4[1];
            bb[0]=u0.x; bb[1]=u0.y; bb[2]=u0.z; bb[3]=u0.w;
            bb[4]=u1.x; bb[5]=u1.y; bb[6]=u1.z; bb[7]=u1.w;
            #pragma unroll
            for (int i = 0; i < 8; i++)
                #pragma unroll
                for (int j = 0; j < 8; j++)
                    acc[i][j] += a[i] * bb[j];
        }
        __syncthreads();
    }
    #pragma unroll
    for (int i = 0; i < 8; i++) {
        int m = bm + ty * 8 + i;
        if (m >= M) continue;
        #pragma unroll
        for (int j = 0; j < 8; j++) {
            int n = bn + tx * 8 + j;
            if (n >= N) continue;
            float v = acc[i][j] + bias[n];
            if (EPI == 1) v = quick_gelu(v);
            if (EPI == 2) v += res[(size_t)m * N + n];
            C[(size_t)m * N + n] = v;
        }
    }
}

// ---------------- flash attention: S=513, d=64, 12 heads, 32 batch ----------------
#define ATTN_SMEM (4 * 64 * 68 * 4)
__global__ void attn_kernel(const float* __restrict__ qkv, float* __restrict__ out)
{
    extern __shared__ float smem[];
    float* Qt = smem;                 // [d][r] stride 68
    float* Kt = Qt + 64 * 68;         // [d][j]
    float* Vs = Kt + 64 * 68;         // [j][d]
    float* Pt = Vs + 64 * 68;         // [j][r]

    int qb = blockIdx.x;   // 0..8
    int h  = blockIdx.y;
    int b  = blockIdx.z;
    int tid = threadIdx.x;
    int tx = tid & 15, ty = tid >> 4;
    int qbase = qb * 64;

    { // load Q (scaled)
        int r = tid >> 2; int d0 = (tid & 3) * 16;
        int t = qbase + r;
        bool valid = (t < Tn);
        const float* qp = qkv + (size_t)(b * Tn + (valid ? t : 0)) * (3 * Cn) + h * HD + d0;
        #pragma unroll
        for (int i = 0; i < 16; i++)
            Qt[(d0 + i) * 68 + r] = valid ? qp[i] * 0.125f : 0.f;
    }
    float m[4], l[4], o[4][4];
    #pragma unroll
    for (int i = 0; i < 4; i++) {
        m[i] = -1e30f; l[i] = 0.f;
        #pragma unroll
        for (int j = 0; j < 4; j++) o[i][j] = 0.f;
    }

    for (int kb = 0; kb < 9; kb++) {
        int kbase = kb * 64;
        __syncthreads();
        { // load K (transposed) and V
            int r = tid >> 2; int d0 = (tid & 3) * 16;
            int t = kbase + r;
            bool valid = (t < Tn);
            const float* kp = qkv + (size_t)(b * Tn + (valid ? t : 0)) * (3 * Cn) + Cn + h * HD + d0;
            const float* vp = kp + Cn;
            #pragma unroll
            for (int i = 0; i < 16; i++) {
                Kt[(d0 + i) * 68 + r] = valid ? kp[i] : 0.f;
                Vs[r * 68 + d0 + i]   = valid ? vp[i] : 0.f;
            }
        }
        __syncthreads();
        float s[4][4];
        #pragma unroll
        for (int i = 0; i < 4; i++)
            #pragma unroll
            for (int j = 0; j < 4; j++) s[i][j] = 0.f;
        for (int k = 0; k < 64; k++) {
            float4 aa = *(const float4*)&Qt[k * 68 + ty * 4];
            float4 bb = *(const float4*)&Kt[k * 68 + tx * 4];
            float av[4] = {aa.x, aa.y, aa.z, aa.w};
            float bv[4] = {bb.x, bb.y, bb.z, bb.w};
            #pragma unroll
            for (int i = 0; i < 4; i++)
                #pragma unroll
                for (int j = 0; j < 4; j++)
                    s[i][j] += av[i] * bv[j];
        }
        // mask invalid keys
        #pragma unroll
        for (int j = 0; j < 4; j++) {
            if (kbase + tx * 4 + j >= Tn) {
                #pragma unroll
                for (int i = 0; i < 4; i++) s[i][j] = -1e30f;
            }
        }
        // online softmax per row (16-lane group shares row)
        #pragma unroll
        for (int i = 0; i < 4; i++) {
            float tm = fmaxf(fmaxf(s[i][0], s[i][1]), fmaxf(s[i][2], s[i][3]));
            #pragma unroll
            for (int off = 1; off < 16; off <<= 1)
                tm = fmaxf(tm, __shfl_xor_sync(0xffffffffu, tm, off));
            float mnew = fmaxf(m[i], tm);
            float sc = expf(m[i] - mnew);
            float rs = 0.f;
            #pragma unroll
            for (int j = 0; j < 4; j++) {
                float p = expf(s[i][j] - mnew);
                s[i][j] = p; rs += p;
            }
            #pragma unroll
            for (int off = 1; off < 16; off <<= 1)
                rs += __shfl_xor_sync(0xffffffffu, rs, off);
            l[i] = l[i] * sc + rs;
            m[i] = mnew;
            #pragma unroll
            for (int j = 0; j < 4; j++) {
                o[i][j] *= sc;
                Pt[(tx * 4 + j) * 68 + ty * 4 + i] = s[i][j];
            }
        }
        __syncthreads();
        // O += P @ V
        for (int k = 0; k < 64; k++) {
            float4 pp = *(const float4*)&Pt[k * 68 + ty * 4];
            float4 vv = *(const float4*)&Vs[k * 68 + tx * 4];
            float pa[4] = {pp.x, pp.y, pp.z, pp.w};
            float va[4] = {vv.x, vv.y, vv.z, vv.w};
            #pragma unroll
            for (int i = 0; i < 4; i++)
                #pragma unroll
                for (int j = 0; j < 4; j++)
                    o[i][j] += pa[i] * va[j];
        }
    }
    #pragma unroll
    for (int i = 0; i < 4; i++) {
        int t = qbase + ty * 4 + i;
        if (t >= Tn) continue;
        float invl = 1.f / l[i];
        #pragma unroll
        for (int j = 0; j < 4; j++)
            out[(size_t)(b * Tn + t) * Cn + h * HD + tx * 4 + j] = o[i][j] * invl;
    }
}

// ---------------- adapter: x2 = x1 + xffn + 0.5 * (qgelu(xffn@Wa1^T+ba1)@Wa2^T+ba2) ----------------
__global__ void adapter_kernel(const float* __restrict__ xffn, const float* __restrict__ x1,
                               const float* __restrict__ Wa1, const float* __restrict__ ba1,
                               const float* __restrict__ Wa2, const float* __restrict__ ba2,
                               float* __restrict__ x2)
{
    int r = blockIdx.x;
    int tid = threadIdx.x;
    __shared__ float xr[Cn];
    __shared__ float tg[ADn];
    const float* xp = xffn + (size_t)r * Cn;
    for (int c = tid; c < Cn; c += 256) xr[c] = xp[c];
    __syncthreads();
    int w = tid >> 5, lane = tid & 31;
    for (int a = w; a < ADn; a += 8) {
        float p = 0.f;
        const float* ww = Wa1 + (size_t)a * Cn;
        for (int c = lane; c < Cn; c += 32) p += xr[c] * ww[c];
        #pragma unroll
        for (int off = 16; off > 0; off >>= 1) p += __shfl_xor_sync(0xffffffffu, p, off);
        if (lane == 0) tg[a] = quick_gelu(p + ba1[a]);
    }
    __syncthreads();
    const float* x1p = x1 + (size_t)r * Cn;
    for (int c = tid; c < Cn; c += 256) {
        float acc = ba2[c];
        const float* w2 = Wa2 + (size_t)c * ADn;
        #pragma unroll
        for (int a = 0; a < ADn; a++) acc += tg[a] * w2[a];
        x2[(size_t)r * Cn + c] = x1p[c] + xr[c] + 0.5f * acc;
    }
}

// ---------------- segment pooling + batchnorm chain ----------------
__global__ void seg_init(int R)
{
    int i = blockIdx.x * blockDim.x + threadIdx.x;
    int total = R * Cn;
    if (i < total) { g_segmax[i] = -1e30f; g_segsum[i] = 0.f; }
    if (i < R) g_segcnt[i] = 0;
    if (i < Cn) { g_colsum[i] = 0.0; g_colsq[i] = 0.0; }
}

__global__ void seg_scatter(const float* __restrict__ src, int featmode,
                            const int* __restrict__ idx)
{
    int i = blockIdx.x;
    int tid = threadIdx.x;
    int srow = featmode ? featRow(i) : i;
    int seg = idx[i];
    const float* xp = src + (size_t)srow * Cn;
    float* sm = g_segmax + (size_t)seg * Cn;
    float* ss = g_segsum + (size_t)seg * Cn;
    if (tid == 0) atomicAdd(&g_segcnt[seg], 1);
    for (int c = tid; c < Cn; c += 256) {
        float v = xp[c];
        atomicAdd(&ss[c], v);
        atomicMaxF(&sm[c], v);
    }
}

__global__ void seg_combine(int R)
{
    int i = blockIdx.x * blockDim.x + threadIdx.x;
    if (i >= R * Cn) return;
    int r = i / Cn;
    int cnt = g_segcnt[r];
    float mx = (cnt > 0) ? g_segmax[i] : 0.f;
    float mean = g_segsum[i] / (float)((cnt > 0) ? cnt : 1);
    g_scomb[i] = mx + mean;
}

__global__ void colstats(int R)
{
    int col = blockIdx.x * blockDim.x + threadIdx.x;
    if (col >= Cn) return;
    int chunk = (R + gridDim.y - 1) / gridDim.y;
    int r0 = blockIdx.y * chunk;
    int r1 = min(r0 + chunk, R);
    float sum = 0.f, sq = 0.f;
    for (int r = r0; r < r1; r++) {
        float v = g_scomb[(size_t)r * Cn + col];
        sum += v; sq += v * v;
    }
    atomicAdd(&g_colsum[col], (double)sum);
    atomicAdd(&g_colsq[col], (double)sq);
}

__global__ void colfinal(int R)
{
    int col = blockIdx.x * blockDim.x + threadIdx.x;
    if (col >= Cn) return;
    double mean = g_colsum[col] / R;
    double var = g_colsq[col] / R - mean * mean;
    if (var < 0.0) var = 0.0;
    g_mean[col] = (float)mean;
    g_rstd[col] = rsqrtf((float)var + EPSf);
}

__global__ void bn_apply(const float* __restrict__ gam, const float* __restrict__ bet,
                         float* __restrict__ out, int R)
{
    int i = blockIdx.x * blockDim.x + threadIdx.x;
    if (i >= R * Cn) return;
    int col = i % Cn;
    float v = (g_scomb[i] - g_mean[col]) * g_rstd[col] * gam[col] + bet[col];
    out[i] = gelu_exact(v);
}

// ---------------- view attention (N1=128 tokens per block, d=2 per head) ----------------
__global__ void view_attn(const float* __restrict__ qkv1, const unsigned char* __restrict__ mask,
                          float* __restrict__ o1)
{
    int blk = blockIdx.x, h = blockIdx.y;
    int t = threadIdx.x;
    __shared__ float kk[N1n][2];
    __shared__ float vv[N1n][2];
    int row = blk * N1n + t;
    const float* base = qkv1 + (size_t)row * 36;
    float q0 = base[h * 2]     * 0.28867513459481287f;  // 12^-0.5
    float q1 = base[h * 2 + 1] * 0.28867513459481287f;
    kk[t][0] = base[12 + h * 2]; kk[t][1] = base[13 + h * 2];
    vv[t][0] = base[24 + h * 2]; vv[t][1] = base[25 + h * 2];
    __syncthreads();
    const unsigned char* mrow = mask + ((size_t)blk * N1n + t) * N1n;
    float mmax = -1e30f;
    #pragma unroll 4
    for (int j = 0; j < N1n; j++) {
        float s = q0 * kk[j][0] + q1 * kk[j][1] + (mrow[j] ? -100000.f : 0.f);
        mmax = fmaxf(mmax, s);
    }
    float l = 0.f, a0 = 0.f, a1 = 0.f;
    #pragma unroll 4
    for (int j = 0; j < N1n; j++) {
        float s = q0 * kk[j][0] + q1 * kk[j][1] + (mrow[j] ? -100000.f : 0.f);
        float p = expf(s - mmax);
        l += p; a0 += p * vv[j][0]; a1 += p * vv[j][1];
    }
    o1[(size_t)row * MIDn + h * 2]     = a0 / l;
    o1[(size_t)row * MIDn + h * 2 + 1] = a1 / l;
}

// ---------------- flat = o1 @ projw^T + projb + feat ----------------
__global__ void smallproj(const float* __restrict__ o1, const float* __restrict__ pw,
                          const float* __restrict__ pb, const float* __restrict__ x2,
                          float* __restrict__ flat)
{
    int i = blockIdx.x;
    int tid = threadIdx.x;
    __shared__ float os[MIDn];
    if (tid < MIDn) os[tid] = o1[(size_t)i * MIDn + tid];
    __syncthreads();
    size_t frow = (size_t)featRow(i);
    for (int c = tid; c < Cn; c += 256) {
        float acc = pb[c];
        const float* w = pw + (size_t)c * MIDn;
        #pragma unroll
        for (int k = 0; k < MIDn; k++) acc += os[k] * w[k];
        flat[(size_t)i * Cn + c] = acc + x2[frow * Cn + c];
    }
}

// ---------------- final fusion: cossim weights, x_sup, output ----------------
__global__ void final_kernel(const float* __restrict__ x2, const float* __restrict__ g3,
                             const float* __restrict__ bview, const int* __restrict__ cluster,
                             const int* __restrict__ fgi, float* __restrict__ out)
{
    int i = blockIdx.x;
    int tid = threadIdx.x;
    size_t xrow = (size_t)featRow(i);
    __shared__ float x3[Cn];
    __shared__ float pv[NV][Cn];
    __shared__ float red[256];
    __shared__ float sims[NV];
    int cl = cluster[i];
    const float* x3p = g3 + (size_t)cl * Cn;
    for (int c = tid; c < Cn; c += 256) x3[c] = x3p[c];
    for (int v = 0; v < NV; v++) {
        int id = fgi[(size_t)v * BG + i];
        const float* pp = bview + ((size_t)v * D1n + id) * Cn;
        for (int c = tid; c < Cn; c += 256) pv[v][c] = pp[c];
    }
    __syncthreads();
    float p = 0.f;
    for (int c = tid; c < Cn; c += 256) p += x3[c] * x3[c];
    float nx3 = fmaxf(sqrtf(blockReduceSum256(p, red)), 1e-8f);
    for (int v = 0; v < NV; v++) {
        float d = 0.f, n = 0.f;
        for (int c = tid; c < Cn; c += 256) {
            float a = pv[v][c];
            d += a * x3[c]; n += a * a;
        }
        d = blockReduceSum256(d, red);
        n = blockReduceSum256(n, red);
        if (tid == 0) {
            float np = fmaxf(sqrtf(n), 1e-8f);
            float cs = d / (np * nx3);
            sims[v] = (cs + 1.f) * 0.5f;
        }
        __syncthreads();
    }
    float ssum = 0.f;
    #pragma unroll
    for (int v = 0; v < NV; v++) ssum += sims[v];
    float inv = 1.f / ssum;
    const float* x2p = x2 + xrow * Cn;
    float* op = out + xrow * Cn;
    for (int c = tid; c < Cn; c += 256) {
        float sup = 0.f;
        #pragma unroll
        for (int v = 0; v < NV; v++) sup += pv[v][c] * sims[v];
        op[c] = x2p[c] + 0.3f * sup * inv;
    }
}

__global__ void cls_copy(const float* __restrict__ x2, float* __restrict__ out)
{
    size_t row = (size_t)blockIdx.x * Tn;
    for (int c = threadIdx.x; c < Cn; c += blockDim.x)
        out[row * Cn + c] = x2[row * Cn + c];
}

// ---------------- host launch ----------------
extern "C" void kernel_launch(void* const* d_in, const int* in_sizes, int n_in,
                              void* d_out, int out_size)
{
    const float* x    = (const float*)d_in[0];
    const float* ln1g = (const float*)d_in[1];
    const float* ln1b = (const float*)d_in[2];
    const float* ln2g = (const float*)d_in[3];
    const float* ln2b = (const float*)d_in[4];
    const float* Wqkv = (const float*)d_in[5];
    const float* bqkv = (const float*)d_in[6];
    const float* Wo   = (const float*)d_in[7];
    const float* bo   = (const float*)d_in[8];
    const float* Wfc  = (const float*)d_in[9];
    const float* bfc  = (const float*)d_in[10];
    const float* Wproj= (const float*)d_in[11];
    const float* bproj= (const float*)d_in[12];
    const float* Wa1  = (const float*)d_in[13];
    const float* ba1  = (const float*)d_in[14];
    const float* Wa2  = (const float*)d_in[15];
    const float* ba2  = (const float*)d_in[16];
    const float* bn3dg= (const float*)d_in[17];
    const float* bn3db= (const float*)d_in[18];
    const float* bn1dg= (const float*)d_in[19];
    const float* bn1db= (const float*)d_in[20];
    const float* n3g  = (const float*)d_in[21];
    const float* n3b  = (const float*)d_in[22];
    const float* aqw  = (const float*)d_in[23];
    const float* aqb  = (const float*)d_in[24];
    const float* apw  = (const float*)d_in[25];
    const float* apb  = (const float*)d_in[26];
    const int*   cluster = (const int*)d_in[27];
    const int*   fgi  = (const int*)d_in[28];
    const unsigned char* mask = (const unsigned char*)d_in[29];
    float* out = (float*)d_out;

    float *y, *qkv, *att, *x1, *hfc, *xffn, *x2, *g3, *bview, *z, *qkv1, *o1v, *flat;
    cudaGetSymbolAddress((void**)&y,     g_y);
    cudaGetSymbolAddress((void**)&qkv,   g_qkv);
    cudaGetSymbolAddress((void**)&att,   g_att);
    cudaGetSymbolAddress((void**)&x1,    g_x1);
    cudaGetSymbolAddress((void**)&hfc,   g_hfc);
    cudaGetSymbolAddress((void**)&xffn,  g_xffn);
    cudaGetSymbolAddress((void**)&x2,    g_x2);
    cudaGetSymbolAddress((void**)&g3,    g_g3);
    cudaGetSymbolAddress((void**)&bview, g_bview);
    cudaGetSymbolAddress((void**)&z,     g_z);
    cudaGetSymbolAddress((void**)&qkv1,  g_qkv1);
    cudaGetSymbolAddress((void**)&o1v,   g_o1);
    cudaGetSymbolAddress((void**)&flat,  g_flat);

    cudaFuncSetAttribute(attn_kernel, cudaFuncAttributeMaxDynamicSharedMemorySize, ATTN_SMEM);

    // 1) LN1 -> y
    ln_kernel<<<MROWS, 256>>>(x, ln1g, ln1b, y, 0);
    // 2) QKV GEMM
    gemm_nt<0><<<dim3((MROWS + 127) / 128, (3 * Cn) / 128), 256>>>(y, Wqkv, bqkv, nullptr, qkv, MROWS, 3 * Cn, Cn);
    // 3) attention
    attn_kernel<<<dim3(9, Hn, Bn), 256, ATTN_SMEM>>>(qkv, att);
    // 4) output proj + residual
    gemm_nt<2><<<dim3((MROWS + 127) / 128, Cn / 128), 256>>>(att, Wo, bo, x, x1, MROWS, Cn, Cn);
    // 5) LN2 -> y
    ln_kernel<<<MROWS, 256>>>(x1, ln2g, ln2b, y, 0);
    // 6) FC + quick_gelu
    gemm_nt<1><<<dim3((MROWS + 127) / 128, FFn / 128), 256>>>(y, Wfc, bfc, nullptr, hfc, MROWS, FFn, Cn);
    // 7) proj
    gemm_nt<0><<<dim3((MROWS + 127) / 128, Cn / 128), 256>>>(hfc, Wproj, bproj, nullptr, xffn, MROWS, Cn, FFn);
    // 8) adapter + residuals -> x2
    adapter_kernel<<<MROWS, 256>>>(xffn, x1, Wa1, ba1, Wa2, ba2, x2);

    // 9) 3d segment pool + BN over clusters
    {
        int total = NCL * Cn;
        seg_init<<<(total + 255) / 256, 256>>>(NCL);
        seg_scatter<<<BG, 256>>>(x2, 1, cluster);
        seg_combine<<<(total + 255) / 256, 256>>>(NCL);
        colstats<<<dim3(3, 16), 256>>>(NCL);
        colfinal<<<3, 256>>>(NCL);
        bn_apply<<<(total + 255) / 256, 256>>>(bn3dg, bn3db, g3, NCL);
    }

    // 10) view branches
    for (int v = 0; v < NV; v++) {
        ln_kernel<<<BG, 256>>>(x2, n3g + v * Cn, n3b + v * Cn, z, 1);
        gemm_nt<0><<<dim3(BG / 128, 1), 256>>>(z, aqw + (size_t)v * 36 * Cn, aqb + v * 36,
                                               nullptr, qkv1, BG, 36, Cn);
        view_attn<<<dim3(NB1, H1n), N1n>>>(qkv1, mask + (size_t)v * NB1 * N1n * N1n, o1v);
        smallproj<<<BG, 256>>>(o1v, apw + (size_t)v * Cn * MIDn, apb + v * Cn, x2, flat);
        int total = D1n * Cn;
        seg_init<<<(total + 255) / 256, 256>>>(D1n);
        seg_scatter<<<BG, 256>>>(flat, 0, fgi + (size_t)v * BG);
        seg_combine<<<(total + 255) / 256, 256>>>(D1n);
        colstats<<<dim3(3, 16), 256>>>(D1n);
        colfinal<<<3, 256>>>(D1n);
        bn_apply<<<(total + 255) / 256, 256>>>(bn1dg + v * Cn, bn1db + v * Cn,
                                               bview + (size_t)v * D1n * Cn, D1n);
    }

    // 11) cossim fusion + output
    final_kernel<<<BG, 256>>>(x2, g3, bview, cluster, fgi, out);
    cls_copy<<<Bn, 256>>>(x2, out);
}

// round 2
// speedup vs baseline: 2.2763x; 2.2763x over previous
#include <cuda_runtime.h>
#include <cuda_bf16.h>
#include <math.h>
#include <stdint.h>

// ---------------- problem constants ----------------
#define Bn    32
#define Gn    512
#define Cn    768
#define Hn    12
#define HD    64
#define Tn    513              // G+1
#define MROWS (Bn*Tn)          // 16416
#define BG    16384
#define FFn   3072
#define ADn   16
#define MIDn  12
#define H1n   6
#define N1n   128
#define NB1   (BG/N1n)         // 128
#define NCL   2048
#define D1n   6272
#define NV    6
#define EPSf  1e-5f

// ---------------- scratch (device globals; no allocation) ----------------
__device__ float  g_y   [MROWS*Cn];
__device__ float  g_qkv [MROWS*3*Cn];
__device__ float  g_att [MROWS*Cn];
__device__ float  g_x1  [MROWS*Cn];
__device__ float  g_hfc [MROWS*FFn];
__device__ float  g_xffn[MROWS*Cn];
__device__ float  g_x2  [MROWS*Cn];
__device__ float  g_scomb [D1n*Cn];
__device__ double g_colsum[Cn];
__device__ double g_colsq [Cn];
__device__ float  g_mean[Cn];
__device__ float  g_rstd[Cn];
__device__ float  g_g3   [NCL*Cn];
__device__ float  g_bview[NV*D1n*Cn];
__device__ float  g_z    [BG*Cn];
__device__ float  g_qkv1 [BG*36];
__device__ float  g_o1   [BG*MIDn];
__device__ float  g_flat [BG*Cn];
// counting-sort segment machinery
__device__ int    g_hist[D1n+1];
__device__ int    g_off [D1n+1];
__device__ int    g_cur [D1n+1];
__device__ int    g_ord [BG];

// ---------------- helpers ----------------
__device__ __forceinline__ float blockReduceSum256(float v, float* red) {
    int tid = threadIdx.x;
    red[tid] = v; __syncthreads();
    #pragma unroll
    for (int o = 128; o > 0; o >>= 1) {
        if (tid < o) red[tid] += red[tid + o];
        __syncthreads();
    }
    float r = red[0];
    __syncthreads();
    return r;
}

__device__ __forceinline__ float quick_gelu(float x) {
    return x / (1.f + expf(-1.702f * x));
}
__device__ __forceinline__ float gelu_exact(float x) {
    return 0.5f * x * (1.f + erff(x * 0.70710678118654752f));
}
__device__ __forceinline__ int featRow(int i) { // i in [0,BG) -> row in (B,513) layout
    return (i >> 9) * Tn + 1 + (i & 511);
}
__device__ __forceinline__ uint32_t f2tf(float f) {
    uint32_t u;
    asm volatile("cvt.rna.tf32.f32 %0, %1;" : "=r"(u) : "f"(f));
    return u;
}

// ---------------- LayerNorm (two-pass, block per row) ----------------
__global__ void ln_kernel(const float* __restrict__ in, const float* __restrict__ g,
                          const float* __restrict__ b, float* __restrict__ out, int featmode)
{
    int r = blockIdx.x;
    int row = featmode ? featRow(r) : r;
    const float* x = in + (size_t)row * Cn;
    __shared__ float xs[Cn];
    __shared__ float red[256];
    int tid = threadIdx.x;
    float s0 = 0.f;
    for (int c = tid; c < Cn; c += 256) { float v = x[c]; xs[c] = v; s0 += v; }
    float mean = blockReduceSum256(s0, red) * (1.f / Cn);
    float s1 = 0.f;
    for (int c = tid; c < Cn; c += 256) { float d = xs[c] - mean; s1 += d * d; }
    float var = blockReduceSum256(s1, red) * (1.f / Cn);
    float inv = rsqrtf(var + EPSf);
    float* op = out + (size_t)r * Cn;
    for (int c = tid; c < Cn; c += 256)
        op[c] = (xs[c] - mean) * inv * g[c] + b[c];
}

// ---------------- tf32 tensor-core NT GEMM ----------------
// C[M,N] = A[M,K] @ W[N,K]^T + bias (+epi).  K % 16 == 0.
// Block tile 128x128xK16, 256 threads, 8 warps in 2(m) x 4(n): warp tile 64x32.
// EPI: 0 = bias, 1 = bias + quick_gelu, 2 = bias + residual
template <int EPI>
__global__ void __launch_bounds__(256) gemm_tf32(
    const float* __restrict__ A, const float* __restrict__ W,
    const float* __restrict__ bias, const float* __restrict__ res,
    float* __restrict__ C, int M, int N, int K)
{
    __shared__ float As[2][128][20];
    __shared__ float Bs[2][128][20];
    int tid = threadIdx.x;
    int bm = blockIdx.x * 128, bn = blockIdx.y * 128;
    int lane = tid & 31, wid = tid >> 5;
    int wm = (wid & 1) * 64, wn = (wid >> 1) * 32;
    int gid = lane >> 2, tg = lane & 3;

    float acc[4][4][4];
    #pragma unroll
    for (int a = 0; a < 4; a++)
        #pragma unroll
        for (int b = 0; b < 4; b++)
            #pragma unroll
            for (int c = 0; c < 4; c++) acc[a][b][c] = 0.f;

    auto prefetch = [&](int kt, int s) {
        int k0 = kt * 16;
        #pragma unroll
        for (int i = 0; i < 2; i++) {
            int r = (tid >> 2) + i * 64;
            int c = (tid & 3) * 4;
            int arow = bm + r;
            const float* asrc = A + (size_t)(arow < M ? arow : 0) * K + k0 + c;
            uint32_t adst = (uint32_t)__cvta_generic_to_shared(&As[s][r][c]);
            int asz = (arow < M) ? 16 : 0;
            asm volatile("cp.async.ca.shared.global [%0], [%1], 16, %2;\n"
                         :: "r"(adst), "l"(asrc), "r"(asz));
            int brow = bn + r;
            const float* bsrc = W + (size_t)(brow < N ? brow : 0) * K + k0 + c;
            uint32_t bdst = (uint32_t)__cvta_generic_to_shared(&Bs[s][r][c]);
            int bsz = (brow < N) ? 16 : 0;
            asm volatile("cp.async.ca.shared.global [%0], [%1], 16, %2;\n"
                         :: "r"(bdst), "l"(bsrc), "r"(bsz));
        }
    };

    int nt = K / 16;
    prefetch(0, 0);
    asm volatile("cp.async.commit_group;\n");
    int buf = 0;
    for (int t = 0; t < nt; t++) {
        asm volatile("cp.async.wait_group 0;\n");
        __syncthreads();
        if (t + 1 < nt) {
            prefetch(t + 1, buf ^ 1);
            asm volatile("cp.async.commit_group;\n");
        }
        #pragma unroll
        for (int kk = 0; kk < 2; kk++) {
            int kb = kk * 8;
            uint32_t af[4][4], bf[4][2];
            #pragma unroll
            for (int mi = 0; mi < 4; mi++) {
                int r = wm + mi * 16 + gid;
                af[mi][0] = f2tf(As[buf][r    ][kb + tg    ]);
                af[mi][1] = f2tf(As[buf][r + 8][kb + tg    ]);
                af[mi][2] = f2tf(As[buf][r    ][kb + tg + 4]);
                af[mi][3] = f2tf(As[buf][r + 8][kb + tg + 4]);
            }
            #pragma unroll
            for (int ni = 0; ni < 4; ni++) {
                int n0 = wn + ni * 8 + gid;
                bf[ni][0] = f2tf(Bs[buf][n0][kb + tg    ]);
                bf[ni][1] = f2tf(Bs[buf][n0][kb + tg + 4]);
            }
            #pragma unroll
            for (int mi = 0; mi < 4; mi++)
                #pragma unroll
                for (int ni = 0; ni < 4; ni++)
                    asm volatile(
                        "mma.sync.aligned.m16n8k8.row.col.f32.tf32.tf32.f32 "
                        "{%0,%1,%2,%3}, {%4,%5,%6,%7}, {%8,%9}, {%0,%1,%2,%3};\n"
                        : "+f"(acc[mi][ni][0]), "+f"(acc[mi][ni][1]),
                          "+f"(acc[mi][ni][2]), "+f"(acc[mi][ni][3])
                        : "r"(af[mi][0]), "r"(af[mi][1]), "r"(af[mi][2]), "r"(af[mi][3]),
                          "r"(bf[ni][0]), "r"(bf[ni][1]));
        }
        __syncthreads();
        buf ^= 1;
    }

    // epilogue
    #pragma unroll
    for (int mi = 0; mi < 4; mi++) {
        #pragma unroll
        for (int ni = 0; ni < 4; ni++) {
            int m0 = bm + wm + mi * 16 + gid;
            int n0 = bn + wn + ni * 8 + tg * 2;
            if (n0 >= N) continue;
            float b0 = bias[n0], b1 = bias[n0 + 1];
            #pragma unroll
            for (int hh = 0; hh < 2; hh++) {
                int m = m0 + hh * 8;
                if (m >= M) continue;
                float v0 = acc[mi][ni][hh * 2 + 0] + b0;
                float v1 = acc[mi][ni][hh * 2 + 1] + b1;
                if (EPI == 1) { v0 = quick_gelu(v0); v1 = quick_gelu(v1); }
                if (EPI == 2) {
                    v0 += res[(size_t)m * N + n0];
                    v1 += res[(size_t)m * N + n0 + 1];
                }
                C[(size_t)m * N + n0]     = v0;
                C[(size_t)m * N + n0 + 1] = v1;
            }
        }
    }
}

// ---------------- flash attention: S=513, d=64, 12 heads, 32 batch ----------------
#define ATTN_SMEM (4 * 64 * 68 * 4)
__global__ void attn_kernel(const float* __restrict__ qkv, float* __restrict__ out)
{
    extern __shared__ float smem[];
    float* Qt = smem;                 // [d][r] stride 68
    float* Kt = Qt + 64 * 68;         // [d][j]
    float* Vs = Kt + 64 * 68;         // [j][d]
    float* Pt = Vs + 64 * 68;         // [j][r]

    int qb = blockIdx.x;   // 0..8
    int h  = blockIdx.y;
    int b  = blockIdx.z;
    int tid = threadIdx.x;
    int tx = tid & 15, ty = tid >> 4;
    int qbase = qb * 64;

    { // load Q (scaled)
        int r = tid >> 2; int d0 = (tid & 3) * 16;
        int t = qbase + r;
        bool valid = (t < Tn);
        const float* qp = qkv + (size_t)(b * Tn + (valid ? t : 0)) * (3 * Cn) + h * HD + d0;
        #pragma unroll
        for (int i = 0; i < 16; i++)
            Qt[(d0 + i) * 68 + r] = valid ? qp[i] * 0.125f : 0.f;
    }
    float m[4], l[4], o[4][4];
    #pragma unroll
    for (int i = 0; i < 4; i++) {
        m[i] = -1e30f; l[i] = 0.f;
        #pragma unroll
        for (int j = 0; j < 4; j++) o[i][j] = 0.f;
    }

    for (int kb = 0; kb < 9; kb++) {
        int kbase = kb * 64;
        __syncthreads();
        { // load K (transposed) and V
            int r = tid >> 2; int d0 = (tid & 3) * 16;
            int t = kbase + r;
            bool valid = (t < Tn);
            const float* kp = qkv + (size_t)(b * Tn + (valid ? t : 0)) * (3 * Cn) + Cn + h * HD + d0;
            const float* vp = kp + Cn;
            #pragma unroll
            for (int i = 0; i < 16; i++) {
                Kt[(d0 + i) * 68 + r] = valid ? kp[i] : 0.f;
                Vs[r * 68 + d0 + i]   = valid ? vp[i] : 0.f;
            }
        }
        __syncthreads();
        float s[4][4];
        #pragma unroll
        for (int i = 0; i < 4; i++)
            #pragma unroll
            for (int j = 0; j < 4; j++) s[i][j] = 0.f;
        for (int k = 0; k < 64; k++) {
            float4 aa = *(const float4*)&Qt[k * 68 + ty * 4];
            float4 bb = *(const float4*)&Kt[k * 68 + tx * 4];
            float av[4] = {aa.x, aa.y, aa.z, aa.w};
            float bv[4] = {bb.x, bb.y, bb.z, bb.w};
            #pragma unroll
            for (int i = 0; i < 4; i++)
                #pragma unroll
                for (int j = 0; j < 4; j++)
                    s[i][j] += av[i] * bv[j];
        }
        #pragma unroll
        for (int j = 0; j < 4; j++) {
            if (kbase + tx * 4 + j >= Tn) {
                #pragma unroll
                for (int i = 0; i < 4; i++) s[i][j] = -1e30f;
            }
        }
        #pragma unroll
        for (int i = 0; i < 4; i++) {
            float tm = fmaxf(fmaxf(s[i][0], s[i][1]), fmaxf(s[i][2], s[i][3]));
            #pragma unroll
            for (int off = 1; off < 16; off <<= 1)
                tm = fmaxf(tm, __shfl_xor_sync(0xffffffffu, tm, off));
            float mnew = fmaxf(m[i], tm);
            float sc = expf(m[i] - mnew);
            float rs = 0.f;
            #pragma unroll
            for (int j = 0; j < 4; j++) {
                float p = expf(s[i][j] - mnew);
                s[i][j] = p; rs += p;
            }
            #pragma unroll
            for (int off = 1; off < 16; off <<= 1)
                rs += __shfl_xor_sync(0xffffffffu, rs, off);
            l[i] = l[i] * sc + rs;
            m[i] = mnew;
            #pragma unroll
            for (int j = 0; j < 4; j++) {
                o[i][j] *= sc;
                Pt[(tx * 4 + j) * 68 + ty * 4 + i] = s[i][j];
            }
        }
        __syncthreads();
        for (int k = 0; k < 64; k++) {
            float4 pp = *(const float4*)&Pt[k * 68 + ty * 4];
            float4 vv = *(const float4*)&Vs[k * 68 + tx * 4];
            float pa[4] = {pp.x, pp.y, pp.z, pp.w};
            float va[4] = {vv.x, vv.y, vv.z, vv.w};
            #pragma unroll
            for (int i = 0; i < 4; i++)
                #pragma unroll
                for (int j = 0; j < 4; j++)
                    o[i][j] += pa[i] * va[j];
        }
    }
    #pragma unroll
    for (int i = 0; i < 4; i++) {
        int t = qbase + ty * 4 + i;
        if (t >= Tn) continue;
        float invl = 1.f / l[i];
        #pragma unroll
        for (int j = 0; j < 4; j++)
            out[(size_t)(b * Tn + t) * Cn + h * HD + tx * 4 + j] = o[i][j] * invl;
    }
}

// ---------------- adapter: x2 = x1 + xffn + 0.5 * (qgelu(xffn@Wa1^T+ba1)@Wa2^T+ba2) ----------------
__global__ void adapter_kernel(const float* __restrict__ xffn, const float* __restrict__ x1,
                               const float* __restrict__ Wa1, const float* __restrict__ ba1,
                               const float* __restrict__ Wa2, const float* __restrict__ ba2,
                               float* __restrict__ x2)
{
    int r = blockIdx.x;
    int tid = threadIdx.x;
    __shared__ float xr[Cn];
    __shared__ float tg[ADn];
    const float* xp = xffn + (size_t)r * Cn;
    for (int c = tid; c < Cn; c += 256) xr[c] = xp[c];
    __syncthreads();
    int w = tid >> 5, lane = tid & 31;
    for (int a = w; a < ADn; a += 8) {
        float p = 0.f;
        const float* ww = Wa1 + (size_t)a * Cn;
        for (int c = lane; c < Cn; c += 32) p += xr[c] * ww[c];
        #pragma unroll
        for (int off = 16; off > 0; off >>= 1) p += __shfl_xor_sync(0xffffffffu, p, off);
        if (lane == 0) tg[a] = quick_gelu(p + ba1[a]);
    }
    __syncthreads();
    const float* x1p = x1 + (size_t)r * Cn;
    for (int c = tid; c < Cn; c += 256) {
        float acc = ba2[c];
        const float* w2 = Wa2 + (size_t)c * ADn;
        #pragma unroll
        for (int a = 0; a < ADn; a++) acc += tg[a] * w2[a];
        x2[(size_t)r * Cn + c] = x1p[c] + xr[c] + 0.5f * acc;
    }
}

// ---------------- counting-sort segment pooling (atomic-free reduce) ----------------
__global__ void pool_init(int R)
{
    int i = blockIdx.x * blockDim.x + threadIdx.x;
    if (i <= R) g_hist[i] = 0;
    if (i < Cn) { g_colsum[i] = 0.0; g_colsq[i] = 0.0; }
}

__global__ void hist_count(const int* __restrict__ idx)
{
    int i = blockIdx.x * blockDim.x + threadIdx.x;
    if (i < BG) atomicAdd(&g_hist[idx[i]], 1);
}

__global__ void scan_kernel(int R)
{
    __shared__ int part[1024];
    int tid = threadIdx.x;
    int chunk = (R + 1023) / 1024;
    int t0 = tid * chunk;
    int s = 0;
    for (int j = 0; j < chunk; j++)
        if (t0 + j < R) s += g_hist[t0 + j];
    part[tid] = s;
    __syncthreads();
    for (int off = 1; off < 1024; off <<= 1) {
        int v = (tid >= off) ? part[tid - off] : 0;
        __syncthreads();
        part[tid] += v;
        __syncthreads();
    }
    int run = (tid > 0) ? part[tid - 1] : 0;
    for (int j = 0; j < chunk; j++) {
        if (t0 + j < R) {
            int c = g_hist[t0 + j];
            g_off[t0 + j] = run;
            g_cur[t0 + j] = run;
            run += c;
        }
    }
    if (tid == 1023) g_off[R] = part[1023];
}

__global__ void seg_place(const int* __restrict__ idx)
{
    int i = blockIdx.x * blockDim.x + threadIdx.x;
    if (i >= BG) return;
    int p = atomicAdd(&g_cur[idx[i]], 1);
    g_ord[p] = i;
}

__global__ void seg_reduce(const float* __restrict__ src, int featmode)
{
    int r = blockIdx.x;
    int tid = threadIdx.x;
    int s0 = g_off[r], s1 = g_off[r + 1];
    float mx0 = -1e30f, mx1 = -1e30f, mx2 = -1e30f;
    float sm0 = 0.f, sm1 = 0.f, sm2 = 0.f;
    for (int j = s0; j < s1; j++) {
        int i = g_ord[j];
        int srow = featmode ? featRow(i) : i;
        const float* p = src + (size_t)srow * Cn;
        float v0 = p[tid], v1 = p[tid + 256], v2 = p[tid + 512];
        mx0 = fmaxf(mx0, v0); sm0 += v0;
        mx1 = fmaxf(mx1, v1); sm1 += v1;
        mx2 = fmaxf(mx2, v2); sm2 += v2;
    }
    int cnt = s1 - s0;
    float inv = 1.f / (float)(cnt > 0 ? cnt : 1);
    float* op = g_scomb + (size_t)r * Cn;
    op[tid]       = (cnt > 0 ? mx0 : 0.f) + sm0 * inv;
    op[tid + 256] = (cnt > 0 ? mx1 : 0.f) + sm1 * inv;
    op[tid + 512] = (cnt > 0 ? mx2 : 0.f) + sm2 * inv;
}

__global__ void colstats(int R)
{
    int col = blockIdx.x * blockDim.x + threadIdx.x;
    if (col >= Cn) return;
    int chunk = (R + gridDim.y - 1) / gridDim.y;
    int r0 = blockIdx.y * chunk;
    int r1 = min(r0 + chunk, R);
    float sum = 0.f, sq = 0.f;
    for (int r = r0; r < r1; r++) {
        float v = g_scomb[(size_t)r * Cn + col];
        sum += v; sq += v * v;
    }
    atomicAdd(&g_colsum[col], (double)sum);
    atomicAdd(&g_colsq[col], (double)sq);
}

__global__ void colfinal(int R)
{
    int col = blockIdx.x * blockDim.x + threadIdx.x;
    if (col >= Cn) return;
    double mean = g_colsum[col] / R;
    double var = g_colsq[col] / R - mean * mean;
    if (var < 0.0) var = 0.0;
    g_mean[col] = (float)mean;
    g_rstd[col] = rsqrtf((float)var + EPSf);
}

__global__ void bn_apply(const float* __restrict__ gam, const float* __restrict__ bet,
                         float* __restrict__ out, int R)
{
    int i = blockIdx.x * blockDim.x + threadIdx.x;
    if (i >= R * Cn) return;
    int col = i % Cn;
    float v = (g_scomb[i] - g_mean[col]) * g_rstd[col] * gam[col] + bet[col];
    out[i] = gelu_exact(v);
}

// ---------------- view attention (N1=128 tokens per block, d=2 per head) ----------------
__global__ void view_attn(const float* __restrict__ qkv1, const unsigned char* __restrict__ mask,
                          float* __restrict__ o1)
{
    int blk = blockIdx.x, h = blockIdx.y;
    int t = threadIdx.x;
    __shared__ float kk[N1n][2];
    __shared__ float vv[N1n][2];
    int row = blk * N1n + t;
    const float* base = qkv1 + (size_t)row * 36;
    float q0 = base[h * 2]     * 0.28867513459481287f;  // 12^-0.5
    float q1 = base[h * 2 + 1] * 0.28867513459481287f;
    kk[t][0] = base[12 + h * 2]; kk[t][1] = base[13 + h * 2];
    vv[t][0] = base[24 + h * 2]; vv[t][1] = base[25 + h * 2];
    __syncthreads();
    const unsigned char* mrow = mask + ((size_t)blk * N1n + t) * N1n;
    float mmax = -1e30f;
    #pragma unroll 4
    for (int j = 0; j < N1n; j++) {
        float s = q0 * kk[j][0] + q1 * kk[j][1] + (mrow[j] ? -100000.f : 0.f);
        mmax = fmaxf(mmax, s);
    }
    float l = 0.f, a0 = 0.f, a1 = 0.f;
    #pragma unroll 4
    for (int j = 0; j < N1n; j++) {
        float s = q0 * kk[j][0] + q1 * kk[j][1] + (mrow[j] ? -100000.f : 0.f);
        float p = expf(s - mmax);
        l += p; a0 += p * vv[j][0]; a1 += p * vv[j][1];
    }
    o1[(size_t)row * MIDn + h * 2]     = a0 / l;
    o1[(size_t)row * MIDn + h * 2 + 1] = a1 / l;
}

// ---------------- flat = o1 @ projw^T + projb + feat ----------------
__global__ void smallproj(const float* __restrict__ o1, const float* __restrict__ pw,
                          const float* __restrict__ pb, const float* __restrict__ x2,
                          float* __restrict__ flat)
{
    int i = blockIdx.x;
    int tid = threadIdx.x;
    __shared__ float os[MIDn];
    if (tid < MIDn) os[tid] = o1[(size_t)i * MIDn + tid];
    __syncthreads();
    size_t frow = (size_t)featRow(i);
    for (int c = tid; c < Cn; c += 256) {
        float acc = pb[c];
        const float* w = pw + (size_t)c * MIDn;
        #pragma unroll
        for (int k = 0; k < MIDn; k++) acc += os[k] * w[k];
        flat[(size_t)i * Cn + c] = acc + x2[frow * Cn + c];
    }
}

// ---------------- final fusion: cossim weights, x_sup, output ----------------
__global__ void final_kernel(const float* __restrict__ x2, const float* __restrict__ g3,
                             const float* __restrict__ bview, const int* __restrict__ cluster,
                             const int* __restrict__ fgi, float* __restrict__ out)
{
    int i = blockIdx.x;
    int tid = threadIdx.x;
    size_t xrow = (size_t)featRow(i);
    __shared__ float x3[Cn];
    __shared__ float pv[NV][Cn];
    __shared__ float red[256];
    __shared__ float sims[NV];
    int cl = cluster[i];
    const float* x3p = g3 + (size_t)cl * Cn;
    for (int c = tid; c < Cn; c += 256) x3[c] = x3p[c];
    for (int v = 0; v < NV; v++) {
        int id = fgi[(size_t)v * BG + i];
        const float* pp = bview + ((size_t)v * D1n + id) * Cn;
        for (int c = tid; c < Cn; c += 256) pv[v][c] = pp[c];
    }
    __syncthreads();
    float p = 0.f;
    for (int c = tid; c < Cn; c += 256) p += x3[c] * x3[c];
    float nx3 = fmaxf(sqrtf(blockReduceSum256(p, red)), 1e-8f);
    for (int v = 0; v < NV; v++) {
        float d = 0.f, n = 0.f;
        for (int c = tid; c < Cn; c += 256) {
            float a = pv[v][c];
            d += a * x3[c]; n += a * a;
        }
        d = blockReduceSum256(d, red);
        n = blockReduceSum256(n, red);
        if (tid == 0) {
            float np = fmaxf(sqrtf(n), 1e-8f);
            float cs = d / (np * nx3);
            sims[v] = (cs + 1.f) * 0.5f;
        }
        __syncthreads();
    }
    float ssum = 0.f;
    #pragma unroll
    for (int v = 0; v < NV; v++) ssum += sims[v];
    float inv = 1.f / ssum;
    const float* x2p = x2 + xrow * Cn;
    float* op = out + xrow * Cn;
    for (int c = tid; c < Cn; c += 256) {
        float sup = 0.f;
        #pragma unroll
        for (int v = 0; v < NV; v++) sup += pv[v][c] * sims[v];
        op[c] = x2p[c] + 0.3f * sup * inv;
    }
}

__global__ void cls_copy(const float* __restrict__ x2, float* __restrict__ out)
{
    size_t row = (size_t)blockIdx.x * Tn;
    for (int c = threadIdx.x; c < Cn; c += blockDim.x)
        out[row * Cn + c] = x2[row * Cn + c];
}

// ---------------- host launch ----------------
extern "C" void kernel_launch(void* const* d_in, const int* in_sizes, int n_in,
                              void* d_out, int out_size)
{
    const float* x    = (const float*)d_in[0];
    const float* ln1g = (const float*)d_in[1];
    const float* ln1b = (const float*)d_in[2];
    const float* ln2g = (const float*)d_in[3];
    const float* ln2b = (const float*)d_in[4];
    const float* Wqkv = (const float*)d_in[5];
    const float* bqkv = (const float*)d_in[6];
    const float* Wo   = (const float*)d_in[7];
    const float* bo   = (const float*)d_in[8];
    const float* Wfc  = (const float*)d_in[9];
    const float* bfc  = (const float*)d_in[10];
    const float* Wproj= (const float*)d_in[11];
    const float* bproj= (const float*)d_in[12];
    const float* Wa1  = (const float*)d_in[13];
    const float* ba1  = (const float*)d_in[14];
    const float* Wa2  = (const float*)d_in[15];
    const float* ba2  = (const float*)d_in[16];
    const float* bn3dg= (const float*)d_in[17];
    const float* bn3db= (const float*)d_in[18];
    const float* bn1dg= (const float*)d_in[19];
    const float* bn1db= (const float*)d_in[20];
    const float* n3g  = (const float*)d_in[21];
    const float* n3b  = (const float*)d_in[22];
    const float* aqw  = (const float*)d_in[23];
    const float* aqb  = (const float*)d_in[24];
    const float* apw  = (const float*)d_in[25];
    const float* apb  = (const float*)d_in[26];
    const int*   cluster = (const int*)d_in[27];
    const int*   fgi  = (const int*)d_in[28];
    const unsigned char* mask = (const unsigned char*)d_in[29];
    float* out = (float*)d_out;

    float *y, *qkv, *att, *x1, *hfc, *xffn, *x2, *g3, *bview, *z, *qkv1, *o1v, *flat;
    cudaGetSymbolAddress((void**)&y,     g_y);
    cudaGetSymbolAddress((void**)&qkv,   g_qkv);
    cudaGetSymbolAddress((void**)&att,   g_att);
    cudaGetSymbolAddress((void**)&x1,    g_x1);
    cudaGetSymbolAddress((void**)&hfc,   g_hfc);
    cudaGetSymbolAddress((void**)&xffn,  g_xffn);
    cudaGetSymbolAddress((void**)&x2,    g_x2);
    cudaGetSymbolAddress((void**)&g3,    g_g3);
    cudaGetSymbolAddress((void**)&bview, g_bview);
    cudaGetSymbolAddress((void**)&z,     g_z);
    cudaGetSymbolAddress((void**)&qkv1,  g_qkv1);
    cudaGetSymbolAddress((void**)&o1v,   g_o1);
    cudaGetSymbolAddress((void**)&flat,  g_flat);

    cudaFuncSetAttribute(attn_kernel, cudaFuncAttributeMaxDynamicSharedMemorySize, ATTN_SMEM);

    const int GMB = (MROWS + 127) / 128;  // 129

    // 1) LN1 -> y
    ln_kernel<<<MROWS, 256>>>(x, ln1g, ln1b, y, 0);
    // 2) QKV GEMM (tf32 tensor core)
    gemm_tf32<0><<<dim3(GMB, (3 * Cn) / 128), 256>>>(y, Wqkv, bqkv, nullptr, qkv, MROWS, 3 * Cn, Cn);
    // 3) attention
    attn_kernel<<<dim3(9, Hn, Bn), 256, ATTN_SMEM>>>(qkv, att);
    // 4) output proj + residual
    gemm_tf32<2><<<dim3(GMB, Cn / 128), 256>>>(att, Wo, bo, x, x1, MROWS, Cn, Cn);
    // 5) LN2 -> y
    ln_kernel<<<MROWS, 256>>>(x1, ln2g, ln2b, y, 0);
    // 6) FC + quick_gelu
    gemm_tf32<1><<<dim3(GMB, FFn / 128), 256>>>(y, Wfc, bfc, nullptr, hfc, MROWS, FFn, Cn);
    // 7) proj
    gemm_tf32<0><<<dim3(GMB, Cn / 128), 256>>>(hfc, Wproj, bproj, nullptr, xffn, MROWS, Cn, FFn);
    // 8) adapter + residuals -> x2
    adapter_kernel<<<MROWS, 256>>>(xffn, x1, Wa1, ba1, Wa2, ba2, x2);

    // 9) 3d segment pool + BN over clusters (counting sort + gather reduce)
    {
        pool_init<<<(NCL + 1 + 255) / 256, 256>>>(NCL);
        hist_count<<<(BG + 255) / 256, 256>>>(cluster);
        scan_kernel<<<1, 1024>>>(NCL);
        seg_place<<<(BG + 255) / 256, 256>>>(cluster);
        seg_reduce<<<NCL, 256>>>(x2, 1);
        colstats<<<dim3(3, 16), 256>>>(NCL);
        colfinal<<<3, 256>>>(NCL);
        bn_apply<<<(NCL * Cn + 255) / 256, 256>>>(bn3dg, bn3db, g3, NCL);
    }

    // 10) view branches
    for (int v = 0; v < NV; v++) {
        ln_kernel<<<BG, 256>>>(x2, n3g + v * Cn, n3b + v * Cn, z, 1);
        gemm_tf32<0><<<dim3(BG / 128, 1), 256>>>(z, aqw + (size_t)v * 36 * Cn, aqb + v * 36,
                                                 nullptr, qkv1, BG, 36, Cn);
        view_attn<<<dim3(NB1, H1n), N1n>>>(qkv1, mask + (size_t)v * NB1 * N1n * N1n, o1v);
        smallproj<<<BG, 256>>>(o1v, apw + (size_t)v * Cn * MIDn, apb + v * Cn, x2, flat);
        pool_init<<<(D1n + 1 + 255) / 256, 256>>>(D1n);
        hist_count<<<(BG + 255) / 256, 256>>>(fgi + (size_t)v * BG);
        scan_kernel<<<1, 1024>>>(D1n);
        seg_place<<<(BG + 255) / 256, 256>>>(fgi + (size_t)v * BG);
        seg_reduce<<<D1n, 256>>>(flat, 0);
        colstats<<<dim3(3, 16), 256>>>(D1n);
        colfinal<<<3, 256>>>(D1n);
        bn_apply<<<(D1n * Cn + 255) / 256, 256>>>(bn1dg + v * Cn, bn1db + v * Cn,
                                                  bview + (size_t)v * D1n * Cn, D1n);
    }

    // 11) cossim fusion + output
    final_kernel<<<BG, 256>>>(x2, g3, bview, cluster, fgi, out);
    cls_copy<<<Bn, 256>>>(x2, out);
}